// round 5
// baseline (speedup 1.0000x reference)
#include <cuda_runtime.h>
#include <math.h>
#include <stdint.h>

// ---------------- problem constants ----------------
#define HW       4096
#define CCH      256
#define S_ELEMS  16777216LL              // 4096*4096
#define NM_ELEMS 2097152LL               // 2*4096*256
#define ZONE_THR 411.041792f             // (0.028^2 * 512^2 * 2)
#define NMS_THR  8.388608f               // (0.004^2 * 512^2 * 2)

// ---------------- device scratch ----------------
static __device__ float g_sim   [2ULL*16777216ULL]; // sim[n][i][j]
static __device__ float g_sim12 [16777216ULL];
static __device__ float g_sim12T[16777216ULL];
static __device__ float g_xn [2097152];             // normalized x1, (n,i,c)
static __device__ float g_rn [2097152];             // normalized x2, (n,c,i)
static __device__ float g_den1[8192];
static __device__ float g_den2[8192];
static __device__ int   g_mid_idx[4096];
static __device__ int   g_max_idx[4096];
static __device__ float g_asim[4096];
static __device__ float g_msim[4096];
static __device__ int   g_mask12[4096];
static __device__ int   g_mask21[4096];
static __device__ int   g_indexA[4096];
static __device__ int   g_indexB[4096];
static __device__ int   g_sigA[4096];
static __device__ int   g_mfA[4096];
static __device__ int   g_sigB[4096];
static __device__ int   g_mfB[4096];
static __device__ long long g_base;

// pdist2, replicating XLA-CPU bit-exactly (unfused squares, FMA dot)
__device__ __forceinline__ float pd2(float ax, float ay, float bx, float by) {
    float sa = __fadd_rn(__fmul_rn(ax, ax), __fmul_rn(ay, ay));
    float sb = __fadd_rn(__fmul_rn(bx, bx), __fmul_rn(by, by));
    float dt = __fmaf_rn(ay, by, __fmul_rn(ax, bx));
    return fabsf(__fsub_rn(__fadd_rn(sa, sb), __fmul_rn(2.0f, dt)));
}

// ---------------- norms per spatial position ----------------
__global__ void norms_kernel(const float* __restrict__ x1, const float* __restrict__ x2) {
    int lane = threadIdx.x & 31, w = threadIdx.x >> 5;
    int n = blockIdx.y;
    int i = blockIdx.x * 32 + lane;
    const float* p1 = x1 + (size_t)n * (CCH * HW) + i;
    const float* p2 = x2 + (size_t)n * (CCH * HW) + i;
    float s1 = 0.f, s2 = 0.f;
    for (int c = w; c < CCH; c += 8) {
        float a = p1[(size_t)c << 12]; s1 += a * a;
        float b = p2[(size_t)c << 12]; s2 += b * b;
    }
    __shared__ float sh1[8][32], sh2[8][32];
    sh1[w][lane] = s1; sh2[w][lane] = s2;
    __syncthreads();
    if (w == 0) {
        float a = 0.f, b = 0.f;
        #pragma unroll
        for (int q = 0; q < 8; q++) { a += sh1[q][lane]; b += sh2[q][lane]; }
        g_den1[n * HW + i] = fmaxf(sqrtf(a), 1e-12f);
        g_den2[n * HW + i] = fmaxf(sqrtf(b), 1e-12f);
    }
}

// normalized x2 in (n,c,i) layout
__global__ void norm_ref_kernel(const float* __restrict__ x2) {
    size_t stride = (size_t)gridDim.x * blockDim.x;
    for (size_t t = (size_t)blockIdx.x * blockDim.x + threadIdx.x; t < (size_t)NM_ELEMS; t += stride) {
        int n = (int)(t >> 20);
        int i = (int)(t & 4095);
        g_rn[t] = x2[t] / g_den2[(n << 12) | i];
    }
}

// normalized x1 transposed to (n,i,c)
__global__ void xpose_norm_kernel(const float* __restrict__ x1) {
    __shared__ float tile[32][33];
    int n = blockIdx.z, c0 = blockIdx.y * 32, i0 = blockIdx.x * 32;
    int tx = threadIdx.x, ty = threadIdx.y;
    for (int r = ty; r < 32; r += 8)
        tile[r][tx] = x1[(size_t)(n * CCH + c0 + r) * HW + i0 + tx];
    __syncthreads();
    for (int r = ty; r < 32; r += 8) {
        int i = i0 + r;
        g_xn[((size_t)(n * HW + i)) * CCH + c0 + tx] = tile[tx][r] / g_den1[n * HW + i];
    }
}

// ================= fused tf32 GEMM + mean + transpose =================
// Per CTA: 128x128 output tile. Both batches computed sequentially; writes
// g_sim[0], g_sim[1], g_sim12 (mean) and g_sim12T (smem transpose).
// 8 warps, warp tile 32x64, k-chunk 32, double-buffered smem pipeline.

#define MT_STRIDE 133
#define FG_MT     0                          // float[128*133] = 68096 B
#define FG_AS0    68096                      // uint32[4096]   = 16384 B
#define FG_BS0    84480                      // uint32[32*136] = 17408 B
#define FG_AS1    101888
#define FG_BS1    118272
#define FG_SMEM   135680

__device__ __forceinline__ uint32_t f2tf32(float f) {
    uint32_t u; asm("cvt.rna.tf32.f32 %0, %1;" : "=r"(u) : "f"(f)); return u;
}
__device__ __forceinline__ void mma_tf32(float* c, const uint32_t* a, const uint32_t* b) {
    asm volatile("mma.sync.aligned.m16n8k8.row.col.f32.tf32.tf32.f32 "
        "{%0,%1,%2,%3}, {%4,%5,%6,%7}, {%8,%9}, {%0,%1,%2,%3};"
        : "+f"(c[0]), "+f"(c[1]), "+f"(c[2]), "+f"(c[3])
        : "r"(a[0]), "r"(a[1]), "r"(a[2]), "r"(a[3]), "r"(b[0]), "r"(b[1]));
}

// load stage: A as fragment gathers (a0,a1,a2,a3 per thread), B as float4 rows
__device__ __forceinline__ void fg_load(const float* __restrict__ A, const float* __restrict__ B,
                                        int m0, int n0, int kc, int tid,
                                        float as[4][4], float4 bs[4]) {
    int lane = tid & 31, w = tid >> 5;
    #pragma unroll
    for (int q = 0; q < 4; q++) {
        int fs = q * 8 + w;
        int mt_ = fs >> 2, ks_ = fs & 3;
        int r_ = mt_ * 16 + (lane >> 2);
        int k_ = ks_ * 8 + (lane & 3);
        const float* p = A + (size_t)(m0 + r_) * CCH + kc + k_;
        as[q][0] = p[0];
        as[q][1] = p[8 * CCH];
        as[q][2] = p[4];
        as[q][3] = p[8 * CCH + 4];
    }
    #pragma unroll
    for (int q = 0; q < 4; q++) {
        int k = 8 * q + w;
        bs[q] = *(const float4*)&B[(size_t)(kc + k) * HW + n0 + 4 * lane];
    }
}
__device__ __forceinline__ void fg_store(uint32_t* __restrict__ As, uint32_t* __restrict__ Bs,
                                         int tid, const float as[4][4], const float4 bs[4]) {
    int lane = tid & 31, w = tid >> 5;
    #pragma unroll
    for (int q = 0; q < 4; q++) {
        int fs = q * 8 + w;
        int mt_ = fs >> 2, ks_ = fs & 3;
        uint4 u = make_uint4(f2tf32(as[q][0]), f2tf32(as[q][1]), f2tf32(as[q][2]), f2tf32(as[q][3]));
        *(uint4*)&As[((mt_ * 4 + ks_) * 32 + lane) * 4] = u;
    }
    #pragma unroll
    for (int q = 0; q < 4; q++) {
        int k = 8 * q + w;
        uint4 u = make_uint4(f2tf32(bs[q].x), f2tf32(bs[q].y), f2tf32(bs[q].z), f2tf32(bs[q].w));
        *(uint4*)&Bs[k * 136 + 4 * lane] = u;
    }
}
__device__ __forceinline__ void fg_compute(const uint32_t* __restrict__ As, const uint32_t* __restrict__ Bs,
                                           int lane, int wm, int wn, float acc[2][8][4]) {
    #pragma unroll
    for (int ks = 0; ks < 4; ks++) {
        uint32_t af[2][4];
        #pragma unroll
        for (int mi = 0; mi < 2; mi++) {
            uint4 t4 = *(const uint4*)&As[(((2 * wm + mi) * 4 + ks) * 32 + lane) * 4];
            af[mi][0] = t4.x; af[mi][1] = t4.y; af[mi][2] = t4.z; af[mi][3] = t4.w;
        }
        #pragma unroll
        for (int nt = 0; nt < 8; nt++) {
            int n = 64 * wn + 8 * nt + (lane >> 2);
            uint32_t bf[2];
            bf[0] = Bs[(ks * 8 + (lane & 3)) * 136 + n];
            bf[1] = Bs[(ks * 8 + (lane & 3) + 4) * 136 + n];
            mma_tf32(acc[0][nt], af[0], bf);
            mma_tf32(acc[1][nt], af[1], bf);
        }
    }
}

__global__ void __launch_bounds__(256) fused_gemm_kernel() {
    extern __shared__ char dsm[];
    float*    mt  = (float*)(dsm + FG_MT);
    uint32_t* AsB[2] = {(uint32_t*)(dsm + FG_AS0), (uint32_t*)(dsm + FG_AS1)};
    uint32_t* BsB[2] = {(uint32_t*)(dsm + FG_BS0), (uint32_t*)(dsm + FG_BS1)};
    int tid = threadIdx.x, lane = tid & 31, w = tid >> 5;
    int wm = w & 3, wn = w >> 2;
    int m0 = blockIdx.y * 128, n0 = blockIdx.x * 128;

    for (int z = 0; z < 2; z++) {
        const float* A  = g_xn  + (size_t)z * (HW * (size_t)CCH);
        const float* B  = g_rn  + (size_t)z * ((size_t)CCH * HW);
        float*       Co = g_sim + (size_t)z * S_ELEMS;

        float acc[2][8][4];
        #pragma unroll
        for (int mi = 0; mi < 2; mi++)
            #pragma unroll
            for (int nt = 0; nt < 8; nt++)
                #pragma unroll
                for (int r = 0; r < 4; r++) acc[mi][nt][r] = 0.f;

        float as[4][4]; float4 bs[4];
        fg_load(A, B, m0, n0, 0, tid, as, bs);
        fg_store(AsB[0], BsB[0], tid, as, bs);
        __syncthreads();
        #pragma unroll 1
        for (int c = 0; c < 8; c++) {
            if (c < 7) fg_load(A, B, m0, n0, (c + 1) * 32, tid, as, bs);
            fg_compute(AsB[c & 1], BsB[c & 1], lane, wm, wn, acc);
            if (c < 7) fg_store(AsB[(c + 1) & 1], BsB[(c + 1) & 1], tid, as, bs);
            __syncthreads();
        }

        // epilogue: write g_sim[z]; accumulate mean tile in smem
        #pragma unroll
        for (int mi = 0; mi < 2; mi++) {
            int lr = 32 * wm + 16 * mi + (lane >> 2);
            #pragma unroll
            for (int nt = 0; nt < 8; nt++) {
                int lc = 64 * wn + 8 * nt + 2 * (lane & 3);
                float2 p0 = make_float2(acc[mi][nt][0], acc[mi][nt][1]);
                float2 p1 = make_float2(acc[mi][nt][2], acc[mi][nt][3]);
                *(float2*)&Co[(size_t)(m0 + lr) * HW + n0 + lc]     = p0;
                *(float2*)&Co[(size_t)(m0 + lr + 8) * HW + n0 + lc] = p1;
                if (z == 0) {
                    mt[lr * MT_STRIDE + lc]           = p0.x;
                    mt[lr * MT_STRIDE + lc + 1]       = p0.y;
                    mt[(lr + 8) * MT_STRIDE + lc]     = p1.x;
                    mt[(lr + 8) * MT_STRIDE + lc + 1] = p1.y;
                } else {
                    float v0 = (mt[lr * MT_STRIDE + lc]           + p0.x) * 0.5f;
                    float v1 = (mt[lr * MT_STRIDE + lc + 1]       + p0.y) * 0.5f;
                    float v2 = (mt[(lr + 8) * MT_STRIDE + lc]     + p1.x) * 0.5f;
                    float v3 = (mt[(lr + 8) * MT_STRIDE + lc + 1] + p1.y) * 0.5f;
                    mt[lr * MT_STRIDE + lc]           = v0;
                    mt[lr * MT_STRIDE + lc + 1]       = v1;
                    mt[(lr + 8) * MT_STRIDE + lc]     = v2;
                    mt[(lr + 8) * MT_STRIDE + lc + 1] = v3;
                    *(float2*)&g_sim12[(size_t)(m0 + lr) * HW + n0 + lc]     = make_float2(v0, v1);
                    *(float2*)&g_sim12[(size_t)(m0 + lr + 8) * HW + n0 + lc] = make_float2(v2, v3);
                }
            }
        }
        if (z == 0) __syncthreads();   // buffers reused next z; mt private per thread
    }
    __syncthreads();
    // transposed write of the mean tile (column reads conflict-free: stride 133)
    #pragma unroll 4
    for (int it = 0; it < 64; it++) {
        int idx = it * 256 + tid;
        int jr = idx >> 7, ic = idx & 127;
        g_sim12T[(size_t)(n0 + jr) * HW + m0 + ic] = mt[ic * MT_STRIDE + jr];
    }
}

// ---------------- association (one block per row) ----------------
__global__ void assoc_kernel(const float* __restrict__ fkpVar, const float* __restrict__ fkpFix, int dir) {
    __shared__ float px[4096], py[4096];
    __shared__ float sv[256]; __shared__ int si[256];
    __shared__ float r0[256], r1[256];
    const float* simM = dir ? g_sim12T : g_sim12;
    int*   oI = dir ? g_max_idx : g_mid_idx;
    float* oS = dir ? g_msim    : g_asim;
    int*   oM = dir ? g_mask21  : g_mask12;

    int i = blockIdx.x, tid = threadIdx.x;
    for (int j = tid; j < HW; j += 256) { px[j] = fkpVar[2 * j]; py[j] = fkpVar[2 * j + 1]; }
    float qx = fkpFix[2 * i], qy = fkpFix[2 * i + 1];
    __syncthreads();
    const float* row = simM + (size_t)i * HW;

    float bv = -INFINITY; int bi = 0x7fffffff;
    for (int j = tid; j < HW; j += 256) {
        float s = row[j];
        float d = pd2(qx, qy, px[j], py[j]);
        float v = s * ((d < ZONE_THR) ? 1.0f : 0.0f);
        if (v > bv || (v == bv && j < bi)) { bv = v; bi = j; }
    }
    sv[tid] = bv; si[tid] = bi;
    __syncthreads();
    for (int o = 128; o > 0; o >>= 1) {
        if (tid < o) {
            float v2 = sv[tid + o]; int i2 = si[tid + o];
            if (v2 > sv[tid] || (v2 == sv[tid] && i2 < si[tid])) { sv[tid] = v2; si[tid] = i2; }
        }
        __syncthreads();
    }
    int idx0 = si[0];
    float rx = px[idx0], ry = py[idx0];

    float t0 = -INFINITY, t1 = -INFINITY;
    for (int j = tid; j < HW; j += 256) {
        float s = row[j];
        float d = pd2(qx, qy, px[j], py[j]);
        float v = s * ((d < ZONE_THR) ? 1.0f : 0.0f);
        float dt = pd2(rx, ry, px[j], py[j]);
        float v2 = v * ((dt >= NMS_THR || dt == 0.0f) ? 1.0f : 0.0f);
        if (v2 > t0) { t1 = t0; t0 = v2; } else if (v2 > t1) { t1 = v2; }
    }
    r0[tid] = t0; r1[tid] = t1;
    __syncthreads();
    for (int o = 128; o > 0; o >>= 1) {
        if (tid < o) {
            float a0 = r0[tid], a1 = r1[tid], b0 = r0[tid + o], b1 = r1[tid + o];
            r0[tid] = fmaxf(a0, b0);
            r1[tid] = fmaxf(fminf(a0, b0), fmaxf(a1, b1));
        }
        __syncthreads();
    }
    if (tid == 0) {
        float v0 = r0[0], v1 = r1[0];
        oI[i] = idx0;
        oS[i] = v0;
        oM[i] = (v1 < v0 * 0.995f && v0 > 0.75f) ? 1 : 0;
    }
}

// ---------------- block scan helper (1024 threads) ----------------
__device__ __forceinline__ int scan1024(int loc, int tid, int* s_warp, int* total) {
    int lane = tid & 31, w = tid >> 5;
    int v = loc;
    #pragma unroll
    for (int o = 1; o < 32; o <<= 1) { int u = __shfl_up_sync(0xffffffffu, v, o); if (lane >= o) v += u; }
    if (lane == 31) s_warp[w] = v;
    __syncthreads();
    if (w == 0) {
        int x = s_warp[lane];
        #pragma unroll
        for (int o = 1; o < 32; o <<= 1) { int u = __shfl_up_sync(0xffffffffu, x, o); if (lane >= o) x += u; }
        s_warp[lane] = x;
    }
    __syncthreads();
    int pre = v - loc + (w ? s_warp[w - 1] : 0);
    *total = s_warp[31];
    __syncthreads();
    return pre;
}

// ---------------- finalize ----------------
__global__ void finalize_kernel(float* __restrict__ out) {
    __shared__ int s_warp[32];
    __shared__ int sh_k12, sh_k21, sh_cm, sh_cm2;
    int tid = threadIdx.x;
    int tot;

    {
        int f[4], loc = 0;
        #pragma unroll
        for (int r = 0; r < 4; r++) { f[r] = g_mask12[tid * 4 + r]; loc += f[r]; }
        int pre = scan1024(loc, tid, s_warp, &tot);
        int p = pre;
        #pragma unroll
        for (int r = 0; r < 4; r++) if (f[r]) g_indexA[p++] = tid * 4 + r;
        if (tid == 0) sh_k12 = tot;
    }
    __syncthreads();
    {
        int f[4], loc = 0;
        #pragma unroll
        for (int r = 0; r < 4; r++) { f[r] = g_mask21[tid * 4 + r]; loc += f[r]; }
        int pre = scan1024(loc, tid, s_warp, &tot);
        int p = pre;
        #pragma unroll
        for (int r = 0; r < 4; r++) if (f[r]) g_indexB[p++] = tid * 4 + r;
        if (tid == 0) sh_k21 = tot;
    }
    __syncthreads();
    int k12 = sh_k12, k21 = sh_k21;

    #pragma unroll
    for (int r = 0; r < 4; r++) {
        int u = tid * 4 + r;
        if (u < k12) {
            int rw = g_indexA[u];
            int mid = g_mid_idx[rw];
            int s21 = g_mask21[mid] ? g_max_idx[mid] : (-g_max_idx[mid] - 2);
            g_sigA[u] = s21;
            g_mfA[u] = (rw == s21) ? 1 : 0;
        } else g_mfA[u] = 0;
        if (u < k21) {
            int rw = g_indexB[u];
            int mx = g_max_idx[rw];
            int s12 = g_mask12[mx] ? g_mid_idx[mx] : (-g_mid_idx[mx] - 2);
            g_sigB[u] = s12;
            g_mfB[u] = (rw == s12) ? 1 : 0;
        } else g_mfB[u] = 0;
    }
    __syncthreads();

    {
        int f[4], loc = 0;
        #pragma unroll
        for (int r = 0; r < 4; r++) { f[r] = g_mfA[tid * 4 + r]; loc += f[r]; }
        int pre = scan1024(loc, tid, s_warp, &tot);
        int p = pre;
        long long o3 = (long long)k12 + 8192;
        #pragma unroll
        for (int r = 0; r < 4; r++) if (f[r]) out[o3 + (p++)] = (float)g_indexA[tid * 4 + r];
        if (tid == 0) sh_cm = tot;
    }
    __syncthreads();
    int cm = sh_cm;
    {
        int f[4], loc = 0;
        #pragma unroll
        for (int r = 0; r < 4; r++) { f[r] = g_mfB[tid * 4 + r]; loc += f[r]; }
        int pre = scan1024(loc, tid, s_warp, &tot);
        int p = pre;
        long long o4 = (long long)k12 + 8192 + cm;
        #pragma unroll
        for (int r = 0; r < 4; r++) if (f[r]) out[o4 + (p++)] = (float)g_indexB[tid * 4 + r];
        if (tid == 0) sh_cm2 = tot;
    }
    __syncthreads();
    int cm2 = sh_cm2;

    for (int u = tid; u < k12; u += 1024) out[u] = (float)g_sigA[u];
    #pragma unroll
    for (int r = 0; r < 4; r++) {
        int u = tid * 4 + r;
        out[(long long)k12 + u]        = (float)g_max_idx[u];
        out[(long long)k12 + 4096 + u] = (float)g_mid_idx[u];
    }
    long long base = (long long)k12 + 8192 + cm + cm2;
    long long o11 = base + 4 * S_ELEMS + 2 * NM_ELEMS;
    #pragma unroll
    for (int r = 0; r < 4; r++) {
        int u = tid * 4 + r;
        out[o11 + u]        = g_mask12[u] ? 1.0f : 0.0f;
        out[o11 + 4096 + u] = g_asim[u];
        out[o11 + 8192 + u] = g_msim[u];
    }
    if (tid == 0) g_base = base;
}

// ---------------- merged big writer ----------------
__global__ void write_rest_kernel(float* __restrict__ out,
                                  const float* __restrict__ fkp1, const float* __restrict__ fkp2) {
    long long b = g_base;
    size_t stride = (size_t)gridDim.x * blockDim.x;
    size_t t0 = (size_t)blockIdx.x * blockDim.x + threadIdx.x;

    for (size_t t = t0; t < (size_t)S_ELEMS; t += stride) {
        out[b + t] = g_sim12[t];
        out[b + S_ELEMS + t] = g_sim12T[t];
    }
    long long o7  = b + 2 * S_ELEMS;
    long long o10 = b + 3 * S_ELEMS + 2 * NM_ELEMS;
    for (size_t t = t0; t < (size_t)S_ELEMS; t += stride) {
        int i = (int)(t >> 12), j = (int)(t & 4095);
        float d = pd2(fkp1[2 * i], fkp1[2 * i + 1], fkp2[2 * j], fkp2[2 * j + 1]);
        out[o7 + t] = (d < ZONE_THR) ? 1.0f : 0.0f;
        out[o10 + t] = d;
    }
    long long o8 = b + 3 * S_ELEMS;
    long long o9 = o8 + NM_ELEMS;
    for (size_t t = t0; t < (size_t)NM_ELEMS; t += stride) {
        out[o8 + t] = g_xn[t];
        out[o9 + t] = g_rn[t];
    }
    long long o14 = b + 4 * S_ELEMS + 2 * NM_ELEMS + 12288;
    for (size_t t = t0; t < (size_t)(2 * S_ELEMS); t += stride) {
        out[o14 + t] = g_sim[t];
    }
}

// ---------------- launcher ----------------
extern "C" void kernel_launch(void* const* d_in, const int* in_sizes, int n_in,
                              void* d_out, int out_size) {
    const float* x1   = (const float*)d_in[0];
    const float* x2   = (const float*)d_in[1];
    const float* fkp1 = (const float*)d_in[2];
    const float* fkp2 = (const float*)d_in[3];
    float* out = (float*)d_out;
    (void)in_sizes; (void)n_in; (void)out_size;

    cudaFuncSetAttribute(fused_gemm_kernel, cudaFuncAttributeMaxDynamicSharedMemorySize, FG_SMEM);

    norms_kernel<<<dim3(128, 2), 256>>>(x1, x2);
    norm_ref_kernel<<<2048, 256>>>(x2);
    xpose_norm_kernel<<<dim3(128, 8, 2), dim3(32, 8)>>>(x1);
    fused_gemm_kernel<<<dim3(32, 32), 256, FG_SMEM>>>();
    assoc_kernel<<<4096, 256>>>(fkp2, fkp1, 0);
    assoc_kernel<<<4096, 256>>>(fkp1, fkp2, 1);
    finalize_kernel<<<1, 1024>>>(out);
    write_rest_kernel<<<8192, 256>>>(out, fkp1, fkp2);
}

// round 6
// speedup vs baseline: 1.5953x; 1.5953x over previous
#include <cuda_runtime.h>
#include <math.h>
#include <stdint.h>

// ---------------- problem constants ----------------
#define HW       4096
#define CCH      256
#define S_ELEMS  16777216LL              // 4096*4096
#define NM_ELEMS 2097152LL               // 2*4096*256
#define ZONE_THR 411.041792f             // (0.028^2 * 512^2 * 2)
#define NMS_THR  8.388608f               // (0.004^2 * 512^2 * 2)

// ---------------- device scratch ----------------
static __device__ float g_sim   [2ULL*16777216ULL]; // sim[n][i][j]
static __device__ float g_sim12 [16777216ULL];
static __device__ float g_sim12T[16777216ULL];
static __device__ float g_xn [2097152];             // normalized x1, (n,i,c)
static __device__ float g_rn [2097152];             // normalized x2, (n,c,i)
static __device__ float g_den1[8192];
static __device__ float g_den2[8192];
static __device__ int   g_mid_idx[4096];
static __device__ int   g_max_idx[4096];
static __device__ float g_asim[4096];
static __device__ float g_msim[4096];
static __device__ int   g_mask12[4096];
static __device__ int   g_mask21[4096];
static __device__ int   g_indexA[4096];
static __device__ int   g_indexB[4096];
static __device__ int   g_sigA[4096];
static __device__ int   g_mfA[4096];
static __device__ int   g_sigB[4096];
static __device__ int   g_mfB[4096];
static __device__ long long g_base;

// pdist2, replicating XLA-CPU bit-exactly (unfused squares, FMA dot)
__device__ __forceinline__ float pd2(float ax, float ay, float bx, float by) {
    float sa = __fadd_rn(__fmul_rn(ax, ax), __fmul_rn(ay, ay));
    float sb = __fadd_rn(__fmul_rn(bx, bx), __fmul_rn(by, by));
    float dt = __fmaf_rn(ay, by, __fmul_rn(ax, bx));
    return fabsf(__fsub_rn(__fadd_rn(sa, sb), __fmul_rn(2.0f, dt)));
}

// ---------------- norms per spatial position ----------------
__global__ void norms_kernel(const float* __restrict__ x1, const float* __restrict__ x2) {
    int lane = threadIdx.x & 31, w = threadIdx.x >> 5;
    int n = blockIdx.y;
    int i = blockIdx.x * 32 + lane;
    const float* p1 = x1 + (size_t)n * (CCH * HW) + i;
    const float* p2 = x2 + (size_t)n * (CCH * HW) + i;
    float s1 = 0.f, s2 = 0.f;
    for (int c = w; c < CCH; c += 8) {
        float a = p1[(size_t)c << 12]; s1 += a * a;
        float b = p2[(size_t)c << 12]; s2 += b * b;
    }
    __shared__ float sh1[8][32], sh2[8][32];
    sh1[w][lane] = s1; sh2[w][lane] = s2;
    __syncthreads();
    if (w == 0) {
        float a = 0.f, b = 0.f;
        #pragma unroll
        for (int q = 0; q < 8; q++) { a += sh1[q][lane]; b += sh2[q][lane]; }
        g_den1[n * HW + i] = fmaxf(sqrtf(a), 1e-12f);
        g_den2[n * HW + i] = fmaxf(sqrtf(b), 1e-12f);
    }
}

// normalized x2 in (n,c,i) layout
__global__ void norm_ref_kernel(const float* __restrict__ x2) {
    size_t stride = (size_t)gridDim.x * blockDim.x;
    for (size_t t = (size_t)blockIdx.x * blockDim.x + threadIdx.x; t < (size_t)NM_ELEMS; t += stride) {
        int n = (int)(t >> 20);
        int i = (int)(t & 4095);
        g_rn[t] = x2[t] / g_den2[(n << 12) | i];
    }
}

// normalized x1 transposed to (n,i,c)
__global__ void xpose_norm_kernel(const float* __restrict__ x1) {
    __shared__ float tile[32][33];
    int n = blockIdx.z, c0 = blockIdx.y * 32, i0 = blockIdx.x * 32;
    int tx = threadIdx.x, ty = threadIdx.y;
    for (int r = ty; r < 32; r += 8)
        tile[r][tx] = x1[(size_t)(n * CCH + c0 + r) * HW + i0 + tx];
    __syncthreads();
    for (int r = ty; r < 32; r += 8) {
        int i = i0 + r;
        g_xn[((size_t)(n * HW + i)) * CCH + c0 + tx] = tile[tx][r] / g_den1[n * HW + i];
    }
}

// ---------------- tf32 tensor-core GEMM (R3-proven) ----------------
__device__ __forceinline__ uint32_t f2tf32(float f) {
    uint32_t u; asm("cvt.rna.tf32.f32 %0, %1;" : "=r"(u) : "f"(f)); return u;
}
__device__ __forceinline__ void mma_tf32(float* c, const uint32_t* a, const uint32_t* b) {
    asm volatile("mma.sync.aligned.m16n8k8.row.col.f32.tf32.tf32.f32 "
        "{%0,%1,%2,%3}, {%4,%5,%6,%7}, {%8,%9}, {%0,%1,%2,%3};"
        : "+f"(c[0]), "+f"(c[1]), "+f"(c[2]), "+f"(c[3])
        : "r"(a[0]), "r"(a[1]), "r"(a[2]), "r"(a[3]), "r"(b[0]), "r"(b[1]));
}

__global__ void __launch_bounds__(256) mma_gemm_kernel() {
    __shared__ uint32_t As[4096];        // [mt(8)][ks(4)][lane(32)][slot(4)]
    __shared__ uint32_t Bs[32][136];     // [k][n], pad 8 -> conflict-free frags
    const float* A  = g_xn + (size_t)blockIdx.z * (HW * (size_t)CCH);
    const float* B  = g_rn + (size_t)blockIdx.z * ((size_t)CCH * HW);
    float*       Co = g_sim + (size_t)blockIdx.z * S_ELEMS;
    int m0 = blockIdx.y * 128, n0 = blockIdx.x * 128;
    int tid = threadIdx.x, lane = tid & 31, w = tid >> 5;
    int wm = w & 3, wn = w >> 2;

    float acc[2][8][4];
    #pragma unroll
    for (int mi = 0; mi < 2; mi++)
        #pragma unroll
        for (int nt = 0; nt < 8; nt++)
            #pragma unroll
            for (int r = 0; r < 4; r++) acc[mi][nt][r] = 0.f;

    for (int kc = 0; kc < CCH; kc += 32) {
        #pragma unroll
        for (int q = 0; q < 4; q++) {
            int m  = 32 * q + (tid >> 3);
            int kb = 4 * (tid & 7);
            float4 v = *(const float4*)&A[(size_t)(m0 + m) * CCH + kc + kb];
            int mt = m >> 4, lm = m & 15;
            float vv[4] = {v.x, v.y, v.z, v.w};
            #pragma unroll
            for (int j = 0; j < 4; j++) {
                int k = kb + j, ks = k >> 3, kk = k & 7;
                int ln   = (lm & 7) * 4 + (kk & 3);
                int slot = (lm >> 3) + ((kk >> 2) << 1);
                As[((mt * 4 + ks) * 32 + ln) * 4 + slot] = f2tf32(vv[j]);
            }
        }
        #pragma unroll
        for (int q = 0; q < 4; q++) {
            int k = 8 * q + (tid >> 5);
            int c = 4 * (tid & 31);
            float4 v = *(const float4*)&B[(size_t)(kc + k) * HW + n0 + c];
            uint4 u;
            u.x = f2tf32(v.x); u.y = f2tf32(v.y); u.z = f2tf32(v.z); u.w = f2tf32(v.w);
            *(uint4*)&Bs[k][c] = u;
        }
        __syncthreads();
        #pragma unroll
        for (int ks = 0; ks < 4; ks++) {
            uint32_t af[2][4];
            #pragma unroll
            for (int mi = 0; mi < 2; mi++) {
                uint4 t4 = *(const uint4*)&As[(((2 * wm + mi) * 4 + ks) * 32 + lane) * 4];
                af[mi][0] = t4.x; af[mi][1] = t4.y; af[mi][2] = t4.z; af[mi][3] = t4.w;
            }
            #pragma unroll
            for (int nt = 0; nt < 8; nt++) {
                uint32_t bf[2];
                int n = 64 * wn + 8 * nt + (lane >> 2);
                bf[0] = Bs[ks * 8 + (lane & 3)][n];
                bf[1] = Bs[ks * 8 + (lane & 3) + 4][n];
                mma_tf32(acc[0][nt], af[0], bf);
                mma_tf32(acc[1][nt], af[1], bf);
            }
        }
        __syncthreads();
    }
    #pragma unroll
    for (int mi = 0; mi < 2; mi++) {
        int row0 = m0 + 32 * wm + 16 * mi + (lane >> 2);
        #pragma unroll
        for (int nt = 0; nt < 8; nt++) {
            int col = n0 + 64 * wn + 8 * nt + 2 * (lane & 3);
            *(float2*)&Co[(size_t)row0 * HW + col]       = make_float2(acc[mi][nt][0], acc[mi][nt][1]);
            *(float2*)&Co[(size_t)(row0 + 8) * HW + col] = make_float2(acc[mi][nt][2], acc[mi][nt][3]);
        }
    }
}

// ---------------- mean over batch + transpose ----------------
__global__ void avg_tr_kernel() {
    __shared__ float tile[32][33];
    int i0 = blockIdx.y * 32, j0 = blockIdx.x * 32;
    int tx = threadIdx.x, ty = threadIdx.y;
    for (int r = ty; r < 32; r += 8) {
        size_t idx = (size_t)(i0 + r) * HW + j0 + tx;
        float v = (g_sim[idx] + g_sim[S_ELEMS + idx]) * 0.5f;
        g_sim12[idx] = v;
        tile[r][tx] = v;
    }
    __syncthreads();
    for (int r = ty; r < 32; r += 8)
        g_sim12T[(size_t)(j0 + r) * HW + i0 + tx] = tile[tx][r];
}

// ---------------- single-pass association ----------------
// Top-3 of v = sim*mz reconstructs the NMS-masked top-2 exactly:
// the only point inside the NMS radius of the top-1 ref point is itself
// (nearest-neighbor dist^2 >= 16 > 8.39), kept iff d_self == 0 bit-exactly.
__global__ void assoc_kernel(const float* __restrict__ fkp1, const float* __restrict__ fkp2) {
    __shared__ float px[4096], py[4096];
    __shared__ float s0[256], s1[256], s2[256], sv[256];
    __shared__ int   si[256];
    int dir = blockIdx.y;
    const float* fkpVar = dir ? fkp1 : fkp2;
    const float* fkpFix = dir ? fkp2 : fkp1;
    const float* simM = dir ? g_sim12T : g_sim12;
    int*   oI = dir ? g_max_idx : g_mid_idx;
    float* oS = dir ? g_msim    : g_asim;
    int*   oM = dir ? g_mask21  : g_mask12;

    int i = blockIdx.x, tid = threadIdx.x;
    for (int j = tid; j < HW; j += 256) { px[j] = fkpVar[2 * j]; py[j] = fkpVar[2 * j + 1]; }
    float qx = fkpFix[2 * i], qy = fkpFix[2 * i + 1];
    __syncthreads();
    const float* row = simM + (size_t)i * HW;

    float t0 = -INFINITY, t1 = -INFINITY, t2 = -INFINITY;
    float bv = -INFINITY; int bi = 0x7fffffff;
    for (int j = tid; j < HW; j += 256) {
        float s = row[j];
        float d = pd2(qx, qy, px[j], py[j]);
        float v = s * ((d < ZONE_THR) ? 1.0f : 0.0f);
        if (v > bv || (v == bv && j < bi)) { bv = v; bi = j; }
        if (v > t0)      { t2 = t1; t1 = t0; t0 = v; }
        else if (v > t1) { t2 = t1; t1 = v; }
        else if (v > t2) { t2 = v; }
    }
    s0[tid] = t0; s1[tid] = t1; s2[tid] = t2;
    sv[tid] = bv; si[tid] = bi;
    __syncthreads();
    for (int o = 128; o > 0; o >>= 1) {
        if (tid < o) {
            // argmax with smallest-index tie-break
            float v2_ = sv[tid + o]; int i2_ = si[tid + o];
            if (v2_ > sv[tid] || (v2_ == sv[tid] && i2_ < si[tid])) { sv[tid] = v2_; si[tid] = i2_; }
            // merge sorted-desc triples
            float a0 = s0[tid], a1 = s1[tid], a2 = s2[tid];
            float b0 = s0[tid + o], b1 = s1[tid + o], b2 = s2[tid + o];
            float r0_, r1_, r2_;
            if (a0 >= b0) {
                if (a1 >= b0) { r0_ = a0; r1_ = a1; r2_ = fmaxf(a2, b0); }
                else          { r0_ = a0; r1_ = b0; r2_ = fmaxf(a1, b1); }
            } else {
                if (b1 >= a0) { r0_ = b0; r1_ = b1; r2_ = fmaxf(b2, a0); }
                else          { r0_ = b0; r1_ = a0; r2_ = fmaxf(b1, a1); }
            }
            s0[tid] = r0_; s1[tid] = r1_; s2[tid] = r2_;
        }
        __syncthreads();
    }
    if (tid == 0) {
        int idx0 = si[0];
        float rx = px[idx0], ry = py[idx0];
        float d_self = pd2(rx, ry, rx, ry);
        float T0 = s0[0], T1 = s1[0], T2 = s2[0];
        float v0, v1;
        if (d_self == 0.0f) { v0 = T0; v1 = T1; }
        else if (T1 >= 0.0f) { v0 = T1; v1 = fmaxf(T2, 0.0f); }
        else { v0 = 0.0f; v1 = T1; }
        oI[i] = idx0;
        oS[i] = v0;
        oM[i] = (v1 < v0 * 0.995f && v0 > 0.75f) ? 1 : 0;
    }
}

// ---------------- block scan helper (1024 threads) ----------------
__device__ __forceinline__ int scan1024(int loc, int tid, int* s_warp, int* total) {
    int lane = tid & 31, w = tid >> 5;
    int v = loc;
    #pragma unroll
    for (int o = 1; o < 32; o <<= 1) { int u = __shfl_up_sync(0xffffffffu, v, o); if (lane >= o) v += u; }
    if (lane == 31) s_warp[w] = v;
    __syncthreads();
    if (w == 0) {
        int x = s_warp[lane];
        #pragma unroll
        for (int o = 1; o < 32; o <<= 1) { int u = __shfl_up_sync(0xffffffffu, x, o); if (lane >= o) x += u; }
        s_warp[lane] = x;
    }
    __syncthreads();
    int pre = v - loc + (w ? s_warp[w - 1] : 0);
    *total = s_warp[31];
    __syncthreads();
    return pre;
}

// ---------------- finalize ----------------
__global__ void finalize_kernel(float* __restrict__ out) {
    __shared__ int s_warp[32];
    __shared__ int sh_k12, sh_k21, sh_cm, sh_cm2;
    int tid = threadIdx.x;
    int tot;

    {
        int f[4], loc = 0;
        #pragma unroll
        for (int r = 0; r < 4; r++) { f[r] = g_mask12[tid * 4 + r]; loc += f[r]; }
        int pre = scan1024(loc, tid, s_warp, &tot);
        int p = pre;
        #pragma unroll
        for (int r = 0; r < 4; r++) if (f[r]) g_indexA[p++] = tid * 4 + r;
        if (tid == 0) sh_k12 = tot;
    }
    __syncthreads();
    {
        int f[4], loc = 0;
        #pragma unroll
        for (int r = 0; r < 4; r++) { f[r] = g_mask21[tid * 4 + r]; loc += f[r]; }
        int pre = scan1024(loc, tid, s_warp, &tot);
        int p = pre;
        #pragma unroll
        for (int r = 0; r < 4; r++) if (f[r]) g_indexB[p++] = tid * 4 + r;
        if (tid == 0) sh_k21 = tot;
    }
    __syncthreads();
    int k12 = sh_k12, k21 = sh_k21;

    #pragma unroll
    for (int r = 0; r < 4; r++) {
        int u = tid * 4 + r;
        if (u < k12) {
            int rw = g_indexA[u];
            int mid = g_mid_idx[rw];
            int s21 = g_mask21[mid] ? g_max_idx[mid] : (-g_max_idx[mid] - 2);
            g_sigA[u] = s21;
            g_mfA[u] = (rw == s21) ? 1 : 0;
        } else g_mfA[u] = 0;
        if (u < k21) {
            int rw = g_indexB[u];
            int mx = g_max_idx[rw];
            int s12 = g_mask12[mx] ? g_mid_idx[mx] : (-g_mid_idx[mx] - 2);
            g_sigB[u] = s12;
            g_mfB[u] = (rw == s12) ? 1 : 0;
        } else g_mfB[u] = 0;
    }
    __syncthreads();

    {
        int f[4], loc = 0;
        #pragma unroll
        for (int r = 0; r < 4; r++) { f[r] = g_mfA[tid * 4 + r]; loc += f[r]; }
        int pre = scan1024(loc, tid, s_warp, &tot);
        int p = pre;
        long long o3 = (long long)k12 + 8192;
        #pragma unroll
        for (int r = 0; r < 4; r++) if (f[r]) out[o3 + (p++)] = (float)g_indexA[tid * 4 + r];
        if (tid == 0) sh_cm = tot;
    }
    __syncthreads();
    int cm = sh_cm;
    {
        int f[4], loc = 0;
        #pragma unroll
        for (int r = 0; r < 4; r++) { f[r] = g_mfB[tid * 4 + r]; loc += f[r]; }
        int pre = scan1024(loc, tid, s_warp, &tot);
        int p = pre;
        long long o4 = (long long)k12 + 8192 + cm;
        #pragma unroll
        for (int r = 0; r < 4; r++) if (f[r]) out[o4 + (p++)] = (float)g_indexB[tid * 4 + r];
        if (tid == 0) sh_cm2 = tot;
    }
    __syncthreads();
    int cm2 = sh_cm2;

    for (int u = tid; u < k12; u += 1024) out[u] = (float)g_sigA[u];
    #pragma unroll
    for (int r = 0; r < 4; r++) {
        int u = tid * 4 + r;
        out[(long long)k12 + u]        = (float)g_max_idx[u];
        out[(long long)k12 + 4096 + u] = (float)g_mid_idx[u];
    }
    long long base = (long long)k12 + 8192 + cm + cm2;
    long long o11 = base + 4 * S_ELEMS + 2 * NM_ELEMS;
    #pragma unroll
    for (int r = 0; r < 4; r++) {
        int u = tid * 4 + r;
        out[o11 + u]        = g_mask12[u] ? 1.0f : 0.0f;
        out[o11 + 4096 + u] = g_asim[u];
        out[o11 + 8192 + u] = g_msim[u];
    }
    if (tid == 0) g_base = base;
}

// ---------------- merged big writer ----------------
__global__ void write_rest_kernel(float* __restrict__ out,
                                  const float* __restrict__ fkp1, const float* __restrict__ fkp2) {
    long long b = g_base;
    size_t stride = (size_t)gridDim.x * blockDim.x;
    size_t t0 = (size_t)blockIdx.x * blockDim.x + threadIdx.x;

    for (size_t t = t0; t < (size_t)S_ELEMS; t += stride) {
        out[b + t] = g_sim12[t];
        out[b + S_ELEMS + t] = g_sim12T[t];
    }
    long long o7  = b + 2 * S_ELEMS;
    long long o10 = b + 3 * S_ELEMS + 2 * NM_ELEMS;
    for (size_t t = t0; t < (size_t)S_ELEMS; t += stride) {
        int i = (int)(t >> 12), j = (int)(t & 4095);
        float d = pd2(fkp1[2 * i], fkp1[2 * i + 1], fkp2[2 * j], fkp2[2 * j + 1]);
        out[o7 + t] = (d < ZONE_THR) ? 1.0f : 0.0f;
        out[o10 + t] = d;
    }
    long long o8 = b + 3 * S_ELEMS;
    long long o9 = o8 + NM_ELEMS;
    for (size_t t = t0; t < (size_t)NM_ELEMS; t += stride) {
        out[o8 + t] = g_xn[t];
        out[o9 + t] = g_rn[t];
    }
    long long o14 = b + 4 * S_ELEMS + 2 * NM_ELEMS + 12288;
    for (size_t t = t0; t < (size_t)(2 * S_ELEMS); t += stride) {
        out[o14 + t] = g_sim[t];
    }
}

// ---------------- launcher ----------------
extern "C" void kernel_launch(void* const* d_in, const int* in_sizes, int n_in,
                              void* d_out, int out_size) {
    const float* x1   = (const float*)d_in[0];
    const float* x2   = (const float*)d_in[1];
    const float* fkp1 = (const float*)d_in[2];
    const float* fkp2 = (const float*)d_in[3];
    float* out = (float*)d_out;
    (void)in_sizes; (void)n_in; (void)out_size;

    norms_kernel<<<dim3(128, 2), 256>>>(x1, x2);
    norm_ref_kernel<<<2048, 256>>>(x2);
    xpose_norm_kernel<<<dim3(128, 8, 2), dim3(32, 8)>>>(x1);
    mma_gemm_kernel<<<dim3(32, 32, 2), 256>>>();
    avg_tr_kernel<<<dim3(128, 128), dim3(32, 8)>>>();
    assoc_kernel<<<dim3(4096, 2), 256>>>(fkp1, fkp2);
    finalize_kernel<<<1, 1024>>>(out);
    write_rest_kernel<<<8192, 256>>>(out, fkp1, fkp2);
}

// round 7
// speedup vs baseline: 1.8146x; 1.1375x over previous
#include <cuda_runtime.h>
#include <math.h>
#include <stdint.h>

// ---------------- problem constants ----------------
#define HW       4096
#define CCH      256
#define S_ELEMS  16777216LL              // 4096*4096
#define NM_ELEMS 2097152LL               // 2*4096*256
#define ZONE_THR 411.041792f             // (0.028^2 * 512^2 * 2)
#define NMS_THR  8.388608f               // (0.004^2 * 512^2 * 2)

// ---------------- device scratch ----------------
static __device__ float g_sim   [2ULL*16777216ULL]; // sim[n][i][j]
static __device__ float g_sim12 [16777216ULL];
static __device__ float g_sim12T[16777216ULL];
static __device__ float g_xn [2097152];             // normalized x1, (n,i,c)
static __device__ float g_rn [2097152];             // normalized x2, (n,c,i)
static __device__ float g_den1[8192];
static __device__ float g_den2[8192];
static __device__ int   g_mid_idx[4096];
static __device__ int   g_max_idx[4096];
static __device__ float g_asim[4096];
static __device__ float g_msim[4096];
static __device__ int   g_mask12[4096];
static __device__ int   g_mask21[4096];
static __device__ int   g_indexA[4096];
static __device__ int   g_indexB[4096];
static __device__ int   g_sigA[4096];
static __device__ int   g_mfA[4096];
static __device__ int   g_sigB[4096];
static __device__ int   g_mfB[4096];
static __device__ long long g_base;

// pdist2, replicating XLA-CPU bit-exactly (unfused squares, FMA dot)
__device__ __forceinline__ float pd2(float ax, float ay, float bx, float by) {
    float sa = __fadd_rn(__fmul_rn(ax, ax), __fmul_rn(ay, ay));
    float sb = __fadd_rn(__fmul_rn(bx, bx), __fmul_rn(by, by));
    float dt = __fmaf_rn(ay, by, __fmul_rn(ax, bx));
    return fabsf(__fsub_rn(__fadd_rn(sa, sb), __fmul_rn(2.0f, dt)));
}

// ---------------- norms per spatial position ----------------
__global__ void norms_kernel(const float* __restrict__ x1, const float* __restrict__ x2) {
    int lane = threadIdx.x & 31, w = threadIdx.x >> 5;
    int n = blockIdx.y;
    int i = blockIdx.x * 32 + lane;
    const float* p1 = x1 + (size_t)n * (CCH * HW) + i;
    const float* p2 = x2 + (size_t)n * (CCH * HW) + i;
    float s1 = 0.f, s2 = 0.f;
    for (int c = w; c < CCH; c += 8) {
        float a = p1[(size_t)c << 12]; s1 += a * a;
        float b = p2[(size_t)c << 12]; s2 += b * b;
    }
    __shared__ float sh1[8][32], sh2[8][32];
    sh1[w][lane] = s1; sh2[w][lane] = s2;
    __syncthreads();
    if (w == 0) {
        float a = 0.f, b = 0.f;
        #pragma unroll
        for (int q = 0; q < 8; q++) { a += sh1[q][lane]; b += sh2[q][lane]; }
        g_den1[n * HW + i] = fmaxf(sqrtf(a), 1e-12f);
        g_den2[n * HW + i] = fmaxf(sqrtf(b), 1e-12f);
    }
}

// normalized x2 in (n,c,i) layout
__global__ void norm_ref_kernel(const float* __restrict__ x2) {
    size_t stride = (size_t)gridDim.x * blockDim.x;
    for (size_t t = (size_t)blockIdx.x * blockDim.x + threadIdx.x; t < (size_t)NM_ELEMS; t += stride) {
        int n = (int)(t >> 20);
        int i = (int)(t & 4095);
        g_rn[t] = x2[t] / g_den2[(n << 12) | i];
    }
}

// normalized x1 transposed to (n,i,c)
__global__ void xpose_norm_kernel(const float* __restrict__ x1) {
    __shared__ float tile[32][33];
    int n = blockIdx.z, c0 = blockIdx.y * 32, i0 = blockIdx.x * 32;
    int tx = threadIdx.x, ty = threadIdx.y;
    for (int r = ty; r < 32; r += 8)
        tile[r][tx] = x1[(size_t)(n * CCH + c0 + r) * HW + i0 + tx];
    __syncthreads();
    for (int r = ty; r < 32; r += 8) {
        int i = i0 + r;
        g_xn[((size_t)(n * HW + i)) * CCH + c0 + tx] = tile[tx][r] / g_den1[n * HW + i];
    }
}

// ---------------- tf32 tensor-core GEMM, cp.async 3-stage pipeline ----------------
// smem per stage: A rows [128][36 words] (pad 4 -> frag reads conflict-free),
//                 B rows [32][136 words] (pad 8 -> frag reads conflict-free).
// Raw fp32 bits used as tf32 operands (HW reads tf32 bits; trunc vs rna).
#define ST_WORDS 8960                    // 128*36 + 32*136
#define ST_BYTES 35840
#define GM_SMEM  (3 * ST_BYTES)

__device__ __forceinline__ uint32_t smem_u32(const void* p) {
    uint32_t a;
    asm("{ .reg .u64 t; cvta.to.shared.u64 t, %1; cvt.u32.u64 %0, t; }" : "=r"(a) : "l"(p));
    return a;
}
__device__ __forceinline__ void cpasync16(uint32_t dst, const void* src) {
    asm volatile("cp.async.cg.shared.global [%0], [%1], 16;" :: "r"(dst), "l"(src));
}
__device__ __forceinline__ void mma_tf32(float* c, const uint32_t* a, const uint32_t* b) {
    asm volatile("mma.sync.aligned.m16n8k8.row.col.f32.tf32.tf32.f32 "
        "{%0,%1,%2,%3}, {%4,%5,%6,%7}, {%8,%9}, {%0,%1,%2,%3};"
        : "+f"(c[0]), "+f"(c[1]), "+f"(c[2]), "+f"(c[3])
        : "r"(a[0]), "r"(a[1]), "r"(a[2]), "r"(a[3]), "r"(b[0]), "r"(b[1]));
}

__global__ void __launch_bounds__(256, 2) mma_gemm_kernel() {
    extern __shared__ float smx[];
    const float* A  = g_xn + (size_t)blockIdx.z * (HW * (size_t)CCH);
    const float* B  = g_rn + (size_t)blockIdx.z * ((size_t)CCH * HW);
    float*       Co = g_sim + (size_t)blockIdx.z * S_ELEMS;
    int m0 = blockIdx.y * 128, n0 = blockIdx.x * 128;
    int tid = threadIdx.x, lane = tid & 31, w = tid >> 5;
    int wm = w & 3, wn = w >> 2;
    uint32_t sbase = smem_u32(smx);

    float acc[2][8][4];
    #pragma unroll
    for (int mi = 0; mi < 2; mi++)
        #pragma unroll
        for (int nt = 0; nt < 8; nt++)
            #pragma unroll
            for (int r = 0; r < 4; r++) acc[mi][nt][r] = 0.f;

    // ---- fill one stage with chunk kc (pure 16B cp.async copies) ----
    auto fill = [&](int stage, int kc) {
        uint32_t sa = sbase + stage * ST_BYTES;
        uint32_t sb = sa + 4608 * 4;
        #pragma unroll
        for (int q = 0; q < 4; q++) {
            int i = q * 256 + tid;
            int m = i >> 3, seg = i & 7;
            cpasync16(sa + (uint32_t)(m * 36 + seg * 4) * 4,
                      A + (size_t)(m0 + m) * CCH + kc + seg * 4);
        }
        #pragma unroll
        for (int q = 0; q < 4; q++) {
            int i = q * 256 + tid;
            int k = i >> 5, seg = i & 31;
            cpasync16(sb + (uint32_t)(k * 136 + seg * 4) * 4,
                      B + (size_t)(kc + k) * HW + n0 + seg * 4);
        }
        asm volatile("cp.async.commit_group;" ::: "memory");
    };

    auto compute = [&](int stage) {
        const float* sa = smx + stage * ST_WORDS;
        const float* sb = sa + 4608;
        #pragma unroll
        for (int ks = 0; ks < 4; ks++) {
            uint32_t af[2][4];
            #pragma unroll
            for (int mi = 0; mi < 2; mi++)
                #pragma unroll
                for (int s = 0; s < 4; s++) {
                    int m = 16 * (2 * wm + mi) + (lane >> 2) + 8 * (s & 1);
                    int k = 8 * ks + (lane & 3) + 4 * (s >> 1);
                    af[mi][s] = __float_as_uint(sa[m * 36 + k]);
                }
            #pragma unroll
            for (int nt = 0; nt < 8; nt++) {
                int nn = 64 * wn + 8 * nt + (lane >> 2);
                uint32_t bf[2];
                bf[0] = __float_as_uint(sb[(8 * ks + (lane & 3)) * 136 + nn]);
                bf[1] = __float_as_uint(sb[(8 * ks + (lane & 3) + 4) * 136 + nn]);
                mma_tf32(acc[0][nt], af[0], bf);
                mma_tf32(acc[1][nt], af[1], bf);
            }
        }
    };

    fill(0, 0);
    fill(1, 32);
    #pragma unroll 1
    for (int c = 0; c < 8; c++) {
        asm volatile("cp.async.wait_group 1;" ::: "memory");
        __syncthreads();                  // stage c ready; all warps done with stage c-1
        if (c < 6) fill((c + 2) % 3, (c + 2) * 32);   // overlaps compute below
        compute(c % 3);
    }

    #pragma unroll
    for (int mi = 0; mi < 2; mi++) {
        int row0 = m0 + 32 * wm + 16 * mi + (lane >> 2);
        #pragma unroll
        for (int nt = 0; nt < 8; nt++) {
            int col = n0 + 64 * wn + 8 * nt + 2 * (lane & 3);
            *(float2*)&Co[(size_t)row0 * HW + col]       = make_float2(acc[mi][nt][0], acc[mi][nt][1]);
            *(float2*)&Co[(size_t)(row0 + 8) * HW + col] = make_float2(acc[mi][nt][2], acc[mi][nt][3]);
        }
    }
}

// ---------------- mean over batch + transpose ----------------
__global__ void avg_tr_kernel() {
    __shared__ float tile[32][33];
    int i0 = blockIdx.y * 32, j0 = blockIdx.x * 32;
    int tx = threadIdx.x, ty = threadIdx.y;
    for (int r = ty; r < 32; r += 8) {
        size_t idx = (size_t)(i0 + r) * HW + j0 + tx;
        float v = (g_sim[idx] + g_sim[S_ELEMS + idx]) * 0.5f;
        g_sim12[idx] = v;
        tile[r][tx] = v;
    }
    __syncthreads();
    for (int r = ty; r < 32; r += 8)
        g_sim12T[(size_t)(j0 + r) * HW + i0 + tx] = tile[tx][r];
}

// ---------------- single-pass association ----------------
// Top-3 of v = sim*mz reconstructs the NMS-masked top-2 exactly:
// the only point inside the NMS radius of the top-1 ref point is itself
// (nearest-neighbor dist^2 >= 16 > 8.39), kept iff d_self == 0 bit-exactly.
__global__ void assoc_kernel(const float* __restrict__ fkp1, const float* __restrict__ fkp2) {
    __shared__ float px[4096], py[4096];
    __shared__ float s0[256], s1[256], s2[256], sv[256];
    __shared__ int   si[256];
    int dir = blockIdx.y;
    const float* fkpVar = dir ? fkp1 : fkp2;
    const float* fkpFix = dir ? fkp2 : fkp1;
    const float* simM = dir ? g_sim12T : g_sim12;
    int*   oI = dir ? g_max_idx : g_mid_idx;
    float* oS = dir ? g_msim    : g_asim;
    int*   oM = dir ? g_mask21  : g_mask12;

    int i = blockIdx.x, tid = threadIdx.x;
    for (int j = tid; j < HW; j += 256) { px[j] = fkpVar[2 * j]; py[j] = fkpVar[2 * j + 1]; }
    float qx = fkpFix[2 * i], qy = fkpFix[2 * i + 1];
    __syncthreads();
    const float* row = simM + (size_t)i * HW;

    float t0 = -INFINITY, t1 = -INFINITY, t2 = -INFINITY;
    float bv = -INFINITY; int bi = 0x7fffffff;
    for (int j = tid; j < HW; j += 256) {
        float s = row[j];
        float d = pd2(qx, qy, px[j], py[j]);
        float v = s * ((d < ZONE_THR) ? 1.0f : 0.0f);
        if (v > bv || (v == bv && j < bi)) { bv = v; bi = j; }
        if (v > t0)      { t2 = t1; t1 = t0; t0 = v; }
        else if (v > t1) { t2 = t1; t1 = v; }
        else if (v > t2) { t2 = v; }
    }
    s0[tid] = t0; s1[tid] = t1; s2[tid] = t2;
    sv[tid] = bv; si[tid] = bi;
    __syncthreads();
    for (int o = 128; o > 0; o >>= 1) {
        if (tid < o) {
            float v2_ = sv[tid + o]; int i2_ = si[tid + o];
            if (v2_ > sv[tid] || (v2_ == sv[tid] && i2_ < si[tid])) { sv[tid] = v2_; si[tid] = i2_; }
            float a0 = s0[tid], a1 = s1[tid], a2 = s2[tid];
            float b0 = s0[tid + o], b1 = s1[tid + o], b2 = s2[tid + o];
            float r0_, r1_, r2_;
            if (a0 >= b0) {
                if (a1 >= b0) { r0_ = a0; r1_ = a1; r2_ = fmaxf(a2, b0); }
                else          { r0_ = a0; r1_ = b0; r2_ = fmaxf(a1, b1); }
            } else {
                if (b1 >= a0) { r0_ = b0; r1_ = b1; r2_ = fmaxf(b2, a0); }
                else          { r0_ = b0; r1_ = a0; r2_ = fmaxf(b1, a1); }
            }
            s0[tid] = r0_; s1[tid] = r1_; s2[tid] = r2_;
        }
        __syncthreads();
    }
    if (tid == 0) {
        int idx0 = si[0];
        float rx = px[idx0], ry = py[idx0];
        float d_self = pd2(rx, ry, rx, ry);
        float T0 = s0[0], T1 = s1[0], T2 = s2[0];
        float v0, v1;
        if (d_self == 0.0f) { v0 = T0; v1 = T1; }
        else if (T1 >= 0.0f) { v0 = T1; v1 = fmaxf(T2, 0.0f); }
        else { v0 = 0.0f; v1 = T1; }
        oI[i] = idx0;
        oS[i] = v0;
        oM[i] = (v1 < v0 * 0.995f && v0 > 0.75f) ? 1 : 0;
    }
}

// ---------------- block scan helper (1024 threads) ----------------
__device__ __forceinline__ int scan1024(int loc, int tid, int* s_warp, int* total) {
    int lane = tid & 31, w = tid >> 5;
    int v = loc;
    #pragma unroll
    for (int o = 1; o < 32; o <<= 1) { int u = __shfl_up_sync(0xffffffffu, v, o); if (lane >= o) v += u; }
    if (lane == 31) s_warp[w] = v;
    __syncthreads();
    if (w == 0) {
        int x = s_warp[lane];
        #pragma unroll
        for (int o = 1; o < 32; o <<= 1) { int u = __shfl_up_sync(0xffffffffu, x, o); if (lane >= o) x += u; }
        s_warp[lane] = x;
    }
    __syncthreads();
    int pre = v - loc + (w ? s_warp[w - 1] : 0);
    *total = s_warp[31];
    __syncthreads();
    return pre;
}

// ---------------- finalize ----------------
__global__ void finalize_kernel(float* __restrict__ out) {
    __shared__ int s_warp[32];
    __shared__ int sh_k12, sh_k21, sh_cm, sh_cm2;
    int tid = threadIdx.x;
    int tot;

    {
        int f[4], loc = 0;
        #pragma unroll
        for (int r = 0; r < 4; r++) { f[r] = g_mask12[tid * 4 + r]; loc += f[r]; }
        int pre = scan1024(loc, tid, s_warp, &tot);
        int p = pre;
        #pragma unroll
        for (int r = 0; r < 4; r++) if (f[r]) g_indexA[p++] = tid * 4 + r;
        if (tid == 0) sh_k12 = tot;
    }
    __syncthreads();
    {
        int f[4], loc = 0;
        #pragma unroll
        for (int r = 0; r < 4; r++) { f[r] = g_mask21[tid * 4 + r]; loc += f[r]; }
        int pre = scan1024(loc, tid, s_warp, &tot);
        int p = pre;
        #pragma unroll
        for (int r = 0; r < 4; r++) if (f[r]) g_indexB[p++] = tid * 4 + r;
        if (tid == 0) sh_k21 = tot;
    }
    __syncthreads();
    int k12 = sh_k12, k21 = sh_k21;

    #pragma unroll
    for (int r = 0; r < 4; r++) {
        int u = tid * 4 + r;
        if (u < k12) {
            int rw = g_indexA[u];
            int mid = g_mid_idx[rw];
            int s21 = g_mask21[mid] ? g_max_idx[mid] : (-g_max_idx[mid] - 2);
            g_sigA[u] = s21;
            g_mfA[u] = (rw == s21) ? 1 : 0;
        } else g_mfA[u] = 0;
        if (u < k21) {
            int rw = g_indexB[u];
            int mx = g_max_idx[rw];
            int s12 = g_mask12[mx] ? g_mid_idx[mx] : (-g_mid_idx[mx] - 2);
            g_sigB[u] = s12;
            g_mfB[u] = (rw == s12) ? 1 : 0;
        } else g_mfB[u] = 0;
    }
    __syncthreads();

    {
        int f[4], loc = 0;
        #pragma unroll
        for (int r = 0; r < 4; r++) { f[r] = g_mfA[tid * 4 + r]; loc += f[r]; }
        int pre = scan1024(loc, tid, s_warp, &tot);
        int p = pre;
        long long o3 = (long long)k12 + 8192;
        #pragma unroll
        for (int r = 0; r < 4; r++) if (f[r]) out[o3 + (p++)] = (float)g_indexA[tid * 4 + r];
        if (tid == 0) sh_cm = tot;
    }
    __syncthreads();
    int cm = sh_cm;
    {
        int f[4], loc = 0;
        #pragma unroll
        for (int r = 0; r < 4; r++) { f[r] = g_mfB[tid * 4 + r]; loc += f[r]; }
        int pre = scan1024(loc, tid, s_warp, &tot);
        int p = pre;
        long long o4 = (long long)k12 + 8192 + cm;
        #pragma unroll
        for (int r = 0; r < 4; r++) if (f[r]) out[o4 + (p++)] = (float)g_indexB[tid * 4 + r];
        if (tid == 0) sh_cm2 = tot;
    }
    __syncthreads();
    int cm2 = sh_cm2;

    for (int u = tid; u < k12; u += 1024) out[u] = (float)g_sigA[u];
    #pragma unroll
    for (int r = 0; r < 4; r++) {
        int u = tid * 4 + r;
        out[(long long)k12 + u]        = (float)g_max_idx[u];
        out[(long long)k12 + 4096 + u] = (float)g_mid_idx[u];
    }
    long long base = (long long)k12 + 8192 + cm + cm2;
    long long o11 = base + 4 * S_ELEMS + 2 * NM_ELEMS;
    #pragma unroll
    for (int r = 0; r < 4; r++) {
        int u = tid * 4 + r;
        out[o11 + u]        = g_mask12[u] ? 1.0f : 0.0f;
        out[o11 + 4096 + u] = g_asim[u];
        out[o11 + 8192 + u] = g_msim[u];
    }
    if (tid == 0) g_base = base;
}

// ---------------- merged big writer ----------------
__global__ void write_rest_kernel(float* __restrict__ out,
                                  const float* __restrict__ fkp1, const float* __restrict__ fkp2) {
    long long b = g_base;
    size_t stride = (size_t)gridDim.x * blockDim.x;
    size_t t0 = (size_t)blockIdx.x * blockDim.x + threadIdx.x;

    for (size_t t = t0; t < (size_t)S_ELEMS; t += stride) {
        out[b + t] = g_sim12[t];
        out[b + S_ELEMS + t] = g_sim12T[t];
    }
    long long o7  = b + 2 * S_ELEMS;
    long long o10 = b + 3 * S_ELEMS + 2 * NM_ELEMS;
    for (size_t t = t0; t < (size_t)S_ELEMS; t += stride) {
        int i = (int)(t >> 12), j = (int)(t & 4095);
        float d = pd2(fkp1[2 * i], fkp1[2 * i + 1], fkp2[2 * j], fkp2[2 * j + 1]);
        out[o7 + t] = (d < ZONE_THR) ? 1.0f : 0.0f;
        out[o10 + t] = d;
    }
    long long o8 = b + 3 * S_ELEMS;
    long long o9 = o8 + NM_ELEMS;
    for (size_t t = t0; t < (size_t)NM_ELEMS; t += stride) {
        out[o8 + t] = g_xn[t];
        out[o9 + t] = g_rn[t];
    }
    long long o14 = b + 4 * S_ELEMS + 2 * NM_ELEMS + 12288;
    for (size_t t = t0; t < (size_t)(2 * S_ELEMS); t += stride) {
        out[o14 + t] = g_sim[t];
    }
}

// ---------------- launcher ----------------
extern "C" void kernel_launch(void* const* d_in, const int* in_sizes, int n_in,
                              void* d_out, int out_size) {
    const float* x1   = (const float*)d_in[0];
    const float* x2   = (const float*)d_in[1];
    const float* fkp1 = (const float*)d_in[2];
    const float* fkp2 = (const float*)d_in[3];
    float* out = (float*)d_out;
    (void)in_sizes; (void)n_in; (void)out_size;

    cudaFuncSetAttribute(mma_gemm_kernel, cudaFuncAttributeMaxDynamicSharedMemorySize, GM_SMEM);

    norms_kernel<<<dim3(128, 2), 256>>>(x1, x2);
    norm_ref_kernel<<<2048, 256>>>(x2);
    xpose_norm_kernel<<<dim3(128, 8, 2), dim3(32, 8)>>>(x1);
    mma_gemm_kernel<<<dim3(32, 32, 2), 256, GM_SMEM>>>();
    avg_tr_kernel<<<dim3(128, 128), dim3(32, 8)>>>();
    assoc_kernel<<<dim3(4096, 2), 256>>>(fkp1, fkp2);
    finalize_kernel<<<1, 1024>>>(out);
    write_rest_kernel<<<8192, 256>>>(out, fkp1, fkp2);
}

// round 8
// speedup vs baseline: 2.0158x; 1.1109x over previous
#include <cuda_runtime.h>
#include <math.h>
#include <stdint.h>

// ---------------- problem constants ----------------
#define HW       4096
#define CCH      256
#define S_ELEMS  16777216LL              // 4096*4096
#define NM_ELEMS 2097152LL               // 2*4096*256
#define ZONE_THR 411.041792f             // (0.028^2 * 512^2 * 2)
#define NMS_THR  8.388608f               // (0.004^2 * 512^2 * 2)

// ---------------- device scratch ----------------
static __device__ float g_sim   [2ULL*16777216ULL]; // sim[n][i][j]
static __device__ float g_sim12 [16777216ULL];
static __device__ float g_sim12T[16777216ULL];
static __device__ float g_xn  [2097152];            // normalized x1, (n,i,c) exact
static __device__ float g_rn  [2097152];            // normalized x2, (n,c,i) exact
static __device__ float g_xn32[2097152];            // tf32-rna rounded copies for GEMM
static __device__ float g_rn32[2097152];
static __device__ float g_den1[8192];
static __device__ float g_den2[8192];
static __device__ int   g_mid_idx[4096];
static __device__ int   g_max_idx[4096];
static __device__ float g_asim[4096];
static __device__ float g_msim[4096];
static __device__ int   g_mask12[4096];
static __device__ int   g_mask21[4096];
static __device__ int   g_indexA[4096];
static __device__ int   g_indexB[4096];
static __device__ int   g_sigA[4096];
static __device__ int   g_mfA[4096];
static __device__ int   g_sigB[4096];
static __device__ int   g_mfB[4096];
static __device__ long long g_base;

// pdist2, replicating XLA-CPU bit-exactly (unfused squares, FMA dot)
__device__ __forceinline__ float pd2(float ax, float ay, float bx, float by) {
    float sa = __fadd_rn(__fmul_rn(ax, ax), __fmul_rn(ay, ay));
    float sb = __fadd_rn(__fmul_rn(bx, bx), __fmul_rn(by, by));
    float dt = __fmaf_rn(ay, by, __fmul_rn(ax, bx));
    return fabsf(__fsub_rn(__fadd_rn(sa, sb), __fmul_rn(2.0f, dt)));
}

__device__ __forceinline__ float tf32rna(float f) {
    uint32_t u; asm("cvt.rna.tf32.f32 %0, %1;" : "=r"(u) : "f"(f));
    return __uint_as_float(u);
}

// ---------------- norms per spatial position ----------------
__global__ void norms_kernel(const float* __restrict__ x1, const float* __restrict__ x2) {
    int lane = threadIdx.x & 31, w = threadIdx.x >> 5;
    int n = blockIdx.y;
    int i = blockIdx.x * 32 + lane;
    const float* p1 = x1 + (size_t)n * (CCH * HW) + i;
    const float* p2 = x2 + (size_t)n * (CCH * HW) + i;
    float s1 = 0.f, s2 = 0.f;
    for (int c = w; c < CCH; c += 8) {
        float a = p1[(size_t)c << 12]; s1 += a * a;
        float b = p2[(size_t)c << 12]; s2 += b * b;
    }
    __shared__ float sh1[8][32], sh2[8][32];
    sh1[w][lane] = s1; sh2[w][lane] = s2;
    __syncthreads();
    if (w == 0) {
        float a = 0.f, b = 0.f;
        #pragma unroll
        for (int q = 0; q < 8; q++) { a += sh1[q][lane]; b += sh2[q][lane]; }
        g_den1[n * HW + i] = fmaxf(sqrtf(a), 1e-12f);
        g_den2[n * HW + i] = fmaxf(sqrtf(b), 1e-12f);
    }
}

// normalized x2 in (n,c,i) layout: exact + tf32-rounded copy
__global__ void norm_ref_kernel(const float* __restrict__ x2) {
    size_t stride = (size_t)gridDim.x * blockDim.x;
    for (size_t t = (size_t)blockIdx.x * blockDim.x + threadIdx.x; t < (size_t)NM_ELEMS; t += stride) {
        int n = (int)(t >> 20);
        int i = (int)(t & 4095);
        float v = x2[t] / g_den2[(n << 12) | i];
        g_rn[t] = v;
        g_rn32[t] = tf32rna(v);
    }
}

// normalized x1 transposed to (n,i,c): exact + tf32-rounded copy
__global__ void xpose_norm_kernel(const float* __restrict__ x1) {
    __shared__ float tile[32][33];
    int n = blockIdx.z, c0 = blockIdx.y * 32, i0 = blockIdx.x * 32;
    int tx = threadIdx.x, ty = threadIdx.y;
    for (int r = ty; r < 32; r += 8)
        tile[r][tx] = x1[(size_t)(n * CCH + c0 + r) * HW + i0 + tx];
    __syncthreads();
    for (int r = ty; r < 32; r += 8) {
        int i = i0 + r;
        float v = tile[tx][r] / g_den1[n * HW + i];
        size_t o = ((size_t)(n * HW + i)) * CCH + c0 + tx;
        g_xn[o] = v;
        g_xn32[o] = tf32rna(v);
    }
}

// ---------------- tf32 tensor-core GEMM, cp.async 3-stage pipeline ----------------
// Inputs are pre-rounded (rna) tf32 bits -> numerics match cvt.rna path.
#define ST_WORDS 8960                    // 128*36 + 32*136
#define ST_BYTES 35840
#define GM_SMEM  (3 * ST_BYTES)

__device__ __forceinline__ uint32_t smem_u32(const void* p) {
    uint32_t a;
    asm("{ .reg .u64 t; cvta.to.shared.u64 t, %1; cvt.u32.u64 %0, t; }" : "=r"(a) : "l"(p));
    return a;
}
__device__ __forceinline__ void cpasync16(uint32_t dst, const void* src) {
    asm volatile("cp.async.cg.shared.global [%0], [%1], 16;" :: "r"(dst), "l"(src));
}
__device__ __forceinline__ void mma_tf32(float* c, const uint32_t* a, const uint32_t* b) {
    asm volatile("mma.sync.aligned.m16n8k8.row.col.f32.tf32.tf32.f32 "
        "{%0,%1,%2,%3}, {%4,%5,%6,%7}, {%8,%9}, {%0,%1,%2,%3};"
        : "+f"(c[0]), "+f"(c[1]), "+f"(c[2]), "+f"(c[3])
        : "r"(a[0]), "r"(a[1]), "r"(a[2]), "r"(a[3]), "r"(b[0]), "r"(b[1]));
}

__global__ void __launch_bounds__(256, 2) mma_gemm_kernel() {
    extern __shared__ float smx[];
    const float* A  = g_xn32 + (size_t)blockIdx.z * (HW * (size_t)CCH);
    const float* B  = g_rn32 + (size_t)blockIdx.z * ((size_t)CCH * HW);
    float*       Co = g_sim + (size_t)blockIdx.z * S_ELEMS;
    int m0 = blockIdx.y * 128, n0 = blockIdx.x * 128;
    int tid = threadIdx.x, lane = tid & 31, w = tid >> 5;
    int wm = w & 3, wn = w >> 2;
    uint32_t sbase = smem_u32(smx);

    float acc[2][8][4];
    #pragma unroll
    for (int mi = 0; mi < 2; mi++)
        #pragma unroll
        for (int nt = 0; nt < 8; nt++)
            #pragma unroll
            for (int r = 0; r < 4; r++) acc[mi][nt][r] = 0.f;

    auto fill = [&](int stage, int kc) {
        uint32_t sa = sbase + stage * ST_BYTES;
        uint32_t sb = sa + 4608 * 4;
        #pragma unroll
        for (int q = 0; q < 4; q++) {
            int i = q * 256 + tid;
            int m = i >> 3, seg = i & 7;
            cpasync16(sa + (uint32_t)(m * 36 + seg * 4) * 4,
                      A + (size_t)(m0 + m) * CCH + kc + seg * 4);
        }
        #pragma unroll
        for (int q = 0; q < 4; q++) {
            int i = q * 256 + tid;
            int k = i >> 5, seg = i & 31;
            cpasync16(sb + (uint32_t)(k * 136 + seg * 4) * 4,
                      B + (size_t)(kc + k) * HW + n0 + seg * 4);
        }
        asm volatile("cp.async.commit_group;" ::: "memory");
    };

    auto compute = [&](int stage) {
        const float* sa = smx + stage * ST_WORDS;
        const float* sb = sa + 4608;
        #pragma unroll
        for (int ks = 0; ks < 4; ks++) {
            uint32_t af[2][4];
            #pragma unroll
            for (int mi = 0; mi < 2; mi++)
                #pragma unroll
                for (int s = 0; s < 4; s++) {
                    int m = 16 * (2 * wm + mi) + (lane >> 2) + 8 * (s & 1);
                    int k = 8 * ks + (lane & 3) + 4 * (s >> 1);
                    af[mi][s] = __float_as_uint(sa[m * 36 + k]);
                }
            #pragma unroll
            for (int nt = 0; nt < 8; nt++) {
                int nn = 64 * wn + 8 * nt + (lane >> 2);
                uint32_t bf[2];
                bf[0] = __float_as_uint(sb[(8 * ks + (lane & 3)) * 136 + nn]);
                bf[1] = __float_as_uint(sb[(8 * ks + (lane & 3) + 4) * 136 + nn]);
                mma_tf32(acc[0][nt], af[0], bf);
                mma_tf32(acc[1][nt], af[1], bf);
            }
        }
    };

    fill(0, 0);
    fill(1, 32);
    #pragma unroll 1
    for (int c = 0; c < 8; c++) {
        asm volatile("cp.async.wait_group 1;" ::: "memory");
        __syncthreads();
        if (c < 6) fill((c + 2) % 3, (c + 2) * 32);
        compute(c % 3);
    }

    #pragma unroll
    for (int mi = 0; mi < 2; mi++) {
        int row0 = m0 + 32 * wm + 16 * mi + (lane >> 2);
        #pragma unroll
        for (int nt = 0; nt < 8; nt++) {
            int col = n0 + 64 * wn + 8 * nt + 2 * (lane & 3);
            *(float2*)&Co[(size_t)row0 * HW + col]       = make_float2(acc[mi][nt][0], acc[mi][nt][1]);
            *(float2*)&Co[(size_t)(row0 + 8) * HW + col] = make_float2(acc[mi][nt][2], acc[mi][nt][3]);
        }
    }
}

// ---------------- mean over batch + transpose ----------------
__global__ void avg_tr_kernel() {
    __shared__ float tile[32][33];
    int i0 = blockIdx.y * 32, j0 = blockIdx.x * 32;
    int tx = threadIdx.x, ty = threadIdx.y;
    for (int r = ty; r < 32; r += 8) {
        size_t idx = (size_t)(i0 + r) * HW + j0 + tx;
        float v = (g_sim[idx] + g_sim[S_ELEMS + idx]) * 0.5f;
        g_sim12[idx] = v;
        tile[r][tx] = v;
    }
    __syncthreads();
    for (int r = ty; r < 32; r += 8)
        g_sim12T[(size_t)(j0 + r) * HW + i0 + tx] = tile[tx][r];
}

// ---------------- single-pass association, 8 rows per block ----------------
// Top-3 of v = sim*mz reconstructs the NMS-masked top-2 exactly (see R6).
__global__ void assoc_kernel(const float* __restrict__ fkp1, const float* __restrict__ fkp2) {
    __shared__ float px[4096], py[4096];
    __shared__ float s0[256], s1[256], s2[256], sv[256];
    __shared__ int   si[256];
    int dir = blockIdx.y;
    const float* fkpVar = dir ? fkp1 : fkp2;
    const float* fkpFix = dir ? fkp2 : fkp1;
    const float* simM = dir ? g_sim12T : g_sim12;
    int*   oI = dir ? g_max_idx : g_mid_idx;
    float* oS = dir ? g_msim    : g_asim;
    int*   oM = dir ? g_mask21  : g_mask12;

    int tid = threadIdx.x;
    for (int j = tid; j < HW; j += 256) { px[j] = fkpVar[2 * j]; py[j] = fkpVar[2 * j + 1]; }
    __syncthreads();

    for (int r = 0; r < 8; r++) {
        int i = blockIdx.x * 8 + r;
        float qx = fkpFix[2 * i], qy = fkpFix[2 * i + 1];
        const float* row = simM + (size_t)i * HW;

        float t0 = -INFINITY, t1 = -INFINITY, t2 = -INFINITY;
        float bv = -INFINITY; int bi = 0x7fffffff;
        #pragma unroll
        for (int it = 0; it < 4; it++) {
            int j0 = (it * 256 + tid) * 4;
            float4 s4 = *(const float4*)&row[j0];
            float ss[4] = {s4.x, s4.y, s4.z, s4.w};
            #pragma unroll
            for (int u = 0; u < 4; u++) {
                int j = j0 + u;
                float d = pd2(qx, qy, px[j], py[j]);
                float v = ss[u] * ((d < ZONE_THR) ? 1.0f : 0.0f);
                if (v > bv) { bv = v; bi = j; }           // increasing j -> earliest tie kept
                if (v > t0)      { t2 = t1; t1 = t0; t0 = v; }
                else if (v > t1) { t2 = t1; t1 = v; }
                else if (v > t2) { t2 = v; }
            }
        }
        s0[tid] = t0; s1[tid] = t1; s2[tid] = t2;
        sv[tid] = bv; si[tid] = bi;
        __syncthreads();
        for (int o = 128; o > 0; o >>= 1) {
            if (tid < o) {
                float v2_ = sv[tid + o]; int i2_ = si[tid + o];
                if (v2_ > sv[tid] || (v2_ == sv[tid] && i2_ < si[tid])) { sv[tid] = v2_; si[tid] = i2_; }
                float a0 = s0[tid], a1 = s1[tid], a2 = s2[tid];
                float b0 = s0[tid + o], b1 = s1[tid + o], b2 = s2[tid + o];
                float r0_, r1_, r2_;
                if (a0 >= b0) {
                    if (a1 >= b0) { r0_ = a0; r1_ = a1; r2_ = fmaxf(a2, b0); }
                    else          { r0_ = a0; r1_ = b0; r2_ = fmaxf(a1, b1); }
                } else {
                    if (b1 >= a0) { r0_ = b0; r1_ = b1; r2_ = fmaxf(b2, a0); }
                    else          { r0_ = b0; r1_ = a0; r2_ = fmaxf(b1, a1); }
                }
                s0[tid] = r0_; s1[tid] = r1_; s2[tid] = r2_;
            }
            __syncthreads();
        }
        if (tid == 0) {
            int idx0 = si[0];
            float rx = px[idx0], ry = py[idx0];
            float d_self = pd2(rx, ry, rx, ry);
            float T0 = s0[0], T1 = s1[0], T2 = s2[0];
            float v0, v1;
            if (d_self == 0.0f) { v0 = T0; v1 = T1; }
            else if (T1 >= 0.0f) { v0 = T1; v1 = fmaxf(T2, 0.0f); }
            else { v0 = 0.0f; v1 = T1; }
            oI[i] = idx0;
            oS[i] = v0;
            oM[i] = (v1 < v0 * 0.995f && v0 > 0.75f) ? 1 : 0;
        }
        __syncthreads();
    }
}

// ---------------- block scan helper (1024 threads) ----------------
__device__ __forceinline__ int scan1024(int loc, int tid, int* s_warp, int* total) {
    int lane = tid & 31, w = tid >> 5;
    int v = loc;
    #pragma unroll
    for (int o = 1; o < 32; o <<= 1) { int u = __shfl_up_sync(0xffffffffu, v, o); if (lane >= o) v += u; }
    if (lane == 31) s_warp[w] = v;
    __syncthreads();
    if (w == 0) {
        int x = s_warp[lane];
        #pragma unroll
        for (int o = 1; o < 32; o <<= 1) { int u = __shfl_up_sync(0xffffffffu, x, o); if (lane >= o) x += u; }
        s_warp[lane] = x;
    }
    __syncthreads();
    int pre = v - loc + (w ? s_warp[w - 1] : 0);
    *total = s_warp[31];
    __syncthreads();
    return pre;
}

// ---------------- finalize ----------------
__global__ void finalize_kernel(float* __restrict__ out) {
    __shared__ int s_warp[32];
    __shared__ int sh_k12, sh_k21, sh_cm, sh_cm2;
    int tid = threadIdx.x;
    int tot;

    {
        int f[4], loc = 0;
        #pragma unroll
        for (int r = 0; r < 4; r++) { f[r] = g_mask12[tid * 4 + r]; loc += f[r]; }
        int pre = scan1024(loc, tid, s_warp, &tot);
        int p = pre;
        #pragma unroll
        for (int r = 0; r < 4; r++) if (f[r]) g_indexA[p++] = tid * 4 + r;
        if (tid == 0) sh_k12 = tot;
    }
    __syncthreads();
    {
        int f[4], loc = 0;
        #pragma unroll
        for (int r = 0; r < 4; r++) { f[r] = g_mask21[tid * 4 + r]; loc += f[r]; }
        int pre = scan1024(loc, tid, s_warp, &tot);
        int p = pre;
        #pragma unroll
        for (int r = 0; r < 4; r++) if (f[r]) g_indexB[p++] = tid * 4 + r;
        if (tid == 0) sh_k21 = tot;
    }
    __syncthreads();
    int k12 = sh_k12, k21 = sh_k21;

    #pragma unroll
    for (int r = 0; r < 4; r++) {
        int u = tid * 4 + r;
        if (u < k12) {
            int rw = g_indexA[u];
            int mid = g_mid_idx[rw];
            int s21 = g_mask21[mid] ? g_max_idx[mid] : (-g_max_idx[mid] - 2);
            g_sigA[u] = s21;
            g_mfA[u] = (rw == s21) ? 1 : 0;
        } else g_mfA[u] = 0;
        if (u < k21) {
            int rw = g_indexB[u];
            int mx = g_max_idx[rw];
            int s12 = g_mask12[mx] ? g_mid_idx[mx] : (-g_mid_idx[mx] - 2);
            g_sigB[u] = s12;
            g_mfB[u] = (rw == s12) ? 1 : 0;
        } else g_mfB[u] = 0;
    }
    __syncthreads();

    {
        int f[4], loc = 0;
        #pragma unroll
        for (int r = 0; r < 4; r++) { f[r] = g_mfA[tid * 4 + r]; loc += f[r]; }
        int pre = scan1024(loc, tid, s_warp, &tot);
        int p = pre;
        long long o3 = (long long)k12 + 8192;
        #pragma unroll
        for (int r = 0; r < 4; r++) if (f[r]) out[o3 + (p++)] = (float)g_indexA[tid * 4 + r];
        if (tid == 0) sh_cm = tot;
    }
    __syncthreads();
    int cm = sh_cm;
    {
        int f[4], loc = 0;
        #pragma unroll
        for (int r = 0; r < 4; r++) { f[r] = g_mfB[tid * 4 + r]; loc += f[r]; }
        int pre = scan1024(loc, tid, s_warp, &tot);
        int p = pre;
        long long o4 = (long long)k12 + 8192 + cm;
        #pragma unroll
        for (int r = 0; r < 4; r++) if (f[r]) out[o4 + (p++)] = (float)g_indexB[tid * 4 + r];
        if (tid == 0) sh_cm2 = tot;
    }
    __syncthreads();
    int cm2 = sh_cm2;

    for (int u = tid; u < k12; u += 1024) out[u] = (float)g_sigA[u];
    #pragma unroll
    for (int r = 0; r < 4; r++) {
        int u = tid * 4 + r;
        out[(long long)k12 + u]        = (float)g_max_idx[u];
        out[(long long)k12 + 4096 + u] = (float)g_mid_idx[u];
    }
    long long base = (long long)k12 + 8192 + cm + cm2;
    long long o11 = base + 4 * S_ELEMS + 2 * NM_ELEMS;
    #pragma unroll
    for (int r = 0; r < 4; r++) {
        int u = tid * 4 + r;
        out[o11 + u]        = g_mask12[u] ? 1.0f : 0.0f;
        out[o11 + 4096 + u] = g_asim[u];
        out[o11 + 8192 + u] = g_msim[u];
    }
    if (tid == 0) g_base = base;
}

// ---------------- merged big writer ----------------
__global__ void write_rest_kernel(float* __restrict__ out,
                                  const float* __restrict__ fkp1, const float* __restrict__ fkp2) {
    long long b = g_base;
    size_t stride = (size_t)gridDim.x * blockDim.x;
    size_t t0 = (size_t)blockIdx.x * blockDim.x + threadIdx.x;

    for (size_t t = t0; t < (size_t)S_ELEMS; t += stride) {
        out[b + t] = g_sim12[t];
        out[b + S_ELEMS + t] = g_sim12T[t];
    }
    long long o7  = b + 2 * S_ELEMS;
    long long o10 = b + 3 * S_ELEMS + 2 * NM_ELEMS;
    for (size_t t = t0; t < (size_t)S_ELEMS; t += stride) {
        int i = (int)(t >> 12), j = (int)(t & 4095);
        float d = pd2(fkp1[2 * i], fkp1[2 * i + 1], fkp2[2 * j], fkp2[2 * j + 1]);
        out[o7 + t] = (d < ZONE_THR) ? 1.0f : 0.0f;
        out[o10 + t] = d;
    }
    long long o8 = b + 3 * S_ELEMS;
    long long o9 = o8 + NM_ELEMS;
    for (size_t t = t0; t < (size_t)NM_ELEMS; t += stride) {
        out[o8 + t] = g_xn[t];
        out[o9 + t] = g_rn[t];
    }
    long long o14 = b + 4 * S_ELEMS + 2 * NM_ELEMS + 12288;
    for (size_t t = t0; t < (size_t)(2 * S_ELEMS); t += stride) {
        out[o14 + t] = g_sim[t];
    }
}

// ---------------- launcher ----------------
extern "C" void kernel_launch(void* const* d_in, const int* in_sizes, int n_in,
                              void* d_out, int out_size) {
    const float* x1   = (const float*)d_in[0];
    const float* x2   = (const float*)d_in[1];
    const float* fkp1 = (const float*)d_in[2];
    const float* fkp2 = (const float*)d_in[3];
    float* out = (float*)d_out;
    (void)in_sizes; (void)n_in; (void)out_size;

    cudaFuncSetAttribute(mma_gemm_kernel, cudaFuncAttributeMaxDynamicSharedMemorySize, GM_SMEM);

    norms_kernel<<<dim3(128, 2), 256>>>(x1, x2);
    norm_ref_kernel<<<2048, 256>>>(x2);
    xpose_norm_kernel<<<dim3(128, 8, 2), dim3(32, 8)>>>(x1);
    mma_gemm_kernel<<<dim3(32, 32, 2), 256, GM_SMEM>>>();
    avg_tr_kernel<<<dim3(128, 128), dim3(32, 8)>>>();
    assoc_kernel<<<dim3(512, 2), 256>>>(fkp1, fkp2);
    finalize_kernel<<<1, 1024>>>(out);
    write_rest_kernel<<<8192, 256>>>(out, fkp1, fkp2);
}